// round 15
// baseline (speedup 1.0000x reference)
#include <cuda_runtime.h>
#include <cuda_fp16.h>
#include <math.h>
#include <stdint.h>

// ---------------- problem constants ----------------
#define DK   4096
#define EE   64
#define TOPK 8
#define BM   128
#define BN   128
#define CHUNK 32                 // K floats per stage (two 16-K halves, split over warps)
#define NSTAGE 128
#define NTHREADS 512
#define FULLM 0xffffffffu
#define WWIN 1e-3f               // recheck window (>=45 sigma of 2-pass error)

// ---------------- smem layout (bytes) ----------------
#define A_STAGE 8192             // [k16(2)][128 rows][32B], single fp16 plane
#define B_STAGE 16384            // [k16][pass][n16][lane] uint4
#define OFF_A 0                  // 3 buffers = 24576
#define OFF_B (3*A_STAGE)                 // 24576
#define OFF_SIMS 0                        // overlay dead A+B after the loop (67584B)
#define LDS_ 132
#define OFF_HSQ  (OFF_B + 4*B_STAGE)      // 90112
#define OFF_INVH (OFF_HSQ + 512*4)        // 92160
#define OFF_INVP (OFF_INVH + 512)         // 92672
#define SMEM_TOTAL (OFF_INVP + 512)       // 93184

__device__ float g_inv_pnorm[BN];
// B fragments: [kt(128)][k16(2)][pass(2)][n16(8)][lane(32)] -> uint4
__device__ uint4 g_bfrag[NSTAGE * 2 * 2 * 8 * 32];

// ---------------- helpers ----------------
__device__ __forceinline__ uint32_t smem_u32(const void* p) {
    uint32_t a;
    asm("{ .reg .u64 t; cvta.to.shared.u64 t, %1; cvt.u32.u64 %0, t; }" : "=r"(a) : "l"(p));
    return a;
}
__device__ __forceinline__ void ldm4(uint32_t* r, uint32_t addr) {
    asm volatile("ldmatrix.sync.aligned.m8n8.x4.shared.b16 {%0,%1,%2,%3}, [%4];"
        : "=r"(r[0]), "=r"(r[1]), "=r"(r[2]), "=r"(r[3]) : "r"(addr));
}
__device__ __forceinline__ uint4 lds128(uint32_t addr) {
    uint4 v;
    asm volatile("ld.shared.v4.u32 {%0,%1,%2,%3}, [%4];"
        : "=r"(v.x), "=r"(v.y), "=r"(v.z), "=r"(v.w) : "r"(addr));
    return v;
}
__device__ __forceinline__ void mma16816(float* c, const uint32_t* a, uint32_t b0, uint32_t b1) {
    asm volatile("mma.sync.aligned.m16n8k16.row.col.f32.f16.f16.f32 "
        "{%0,%1,%2,%3}, {%4,%5,%6,%7}, {%8,%9}, {%0,%1,%2,%3};"
        : "+f"(c[0]), "+f"(c[1]), "+f"(c[2]), "+f"(c[3])
        : "r"(a[0]), "r"(a[1]), "r"(a[2]), "r"(a[3]), "r"(b0), "r"(b1));
}
__device__ __forceinline__ void split2(float x, float y, uint32_t& uh, uint32_t& ul) {
    asm("cvt.rn.f16x2.f32 %0, %1, %2;" : "=r"(uh) : "f"(y), "f"(x));
    float lx = __half2float(__ushort_as_half((unsigned short)(uh & 0xffffu)));
    float ly = __half2float(__ushort_as_half((unsigned short)(uh >> 16)));
    float rx = x - lx, ry = y - ly;
    asm("cvt.rn.f16x2.f32 %0, %1, %2;" : "=r"(ul) : "f"(ry), "f"(rx));
}
__device__ __forceinline__ uint32_t cvt2(float x, float y) {
    uint32_t u;
    asm("cvt.rn.f16x2.f32 %0, %1, %2;" : "=r"(u) : "f"(y), "f"(x));
    return u;
}
#define CP_ASYNC16(dst, src) \
    asm volatile("cp.async.cg.shared.global [%0], [%1], 16;" :: "r"(dst), "l"(src))
#define CP_COMMIT() asm volatile("cp.async.commit_group;" ::: "memory")
#define CP_WAIT1()  asm volatile("cp.async.wait_group 1;"  ::: "memory")

// exact fp32 logit for one expert (warp-collective)
__device__ float exact_logit(const float* __restrict__ hrow,
                             const float* __restrict__ proto,
                             int e, float ih, const float* invp, int lane) {
    const float4* h4  = (const float4*)hrow;
    const float4* p4a = (const float4*)(proto + (size_t)(2 * e) * DK);
    const float4* p4b = (const float4*)(proto + (size_t)(2 * e + 1) * DK);
    float d0 = 0.f, d1 = 0.f;
    for (int i = lane; i < DK / 4; i += 32) {
        float4 hv = h4[i], pa = p4a[i], pb = p4b[i];
        d0 += hv.x * pa.x + hv.y * pa.y + hv.z * pa.z + hv.w * pa.w;
        d1 += hv.x * pb.x + hv.y * pb.y + hv.z * pb.z + hv.w * pb.w;
    }
    for (int o = 16; o; o >>= 1) {
        d0 += __shfl_xor_sync(FULLM, d0, o);
        d1 += __shfl_xor_sync(FULLM, d1, o);
    }
    float s0 = d0 * ih * invp[2 * e];
    float s1 = d1 * ih * invp[2 * e + 1];
    float m = fmaxf(s0, s1);
    return 10.0f * (m + logf(expf(s0 - m) + expf(s1 - m)));
}

// ---------------------------------------------------------------------------
// Kernel 1: fused prep — blocks [0,512): B split; blocks [512,640): proto norms
// ---------------------------------------------------------------------------
__global__ void prep_kernel(const float* __restrict__ proto) {
    if (blockIdx.x < 512) {
        int idx  = blockIdx.x * 256 + threadIdx.x;     // 131072 uint4
        int lane = idx & 31;
        int n16  = (idx >> 5) & 7;
        int pass = (idx >> 8) & 1;
        int k16  = (idx >> 9) & 1;
        int kt   = idx >> 10;
        int kt16 = kt * 2 + k16;
        uint32_t w[4];
#pragma unroll
        for (int r = 0; r < 4; r++) {
            int n  = n16 * 16 + ((r & 2) << 2) + (lane >> 2);
            int k0 = kt16 * 16 + (r & 1) * 8 + 2 * (lane & 3);
            float x = proto[(size_t)n * DK + k0];
            float y = proto[(size_t)n * DK + k0 + 1];
            uint32_t uh, ul;
            split2(x, y, uh, ul);
            w[r] = pass ? ul : uh;
        }
        g_bfrag[idx] = make_uint4(w[0], w[1], w[2], w[3]);
    } else {
        int row = blockIdx.x - 512;
        const float4* p = reinterpret_cast<const float4*>(proto + (size_t)row * DK);
        float s = 0.f;
        for (int i = threadIdx.x; i < DK / 4; i += blockDim.x) {
            float4 v = p[i];
            s += v.x * v.x + v.y * v.y + v.z * v.z + v.w * v.w;
        }
        for (int o = 16; o; o >>= 1) s += __shfl_down_sync(FULLM, s, o);
        __shared__ float sm[8];
        if ((threadIdx.x & 31) == 0) sm[threadIdx.x >> 5] = s;
        __syncthreads();
        if (threadIdx.x == 0) {
            float t = 0.f;
            for (int i = 0; i < (int)(blockDim.x >> 5); i++) t += sm[i];
            g_inv_pnorm[row] = 1.0f / (sqrtf(t) + 1e-6f);
        }
    }
}

// ---------------------------------------------------------------------------
// Kernel 2: 2-pass fp16 mma GEMM, K-split 64x32 warp tiles, minimal LDS/issue
//   16 warps = 2 K-groups x (2m x 4n); triple-buffered A; pre-barrier preloads
// ---------------------------------------------------------------------------
extern "C" __global__ void __launch_bounds__(NTHREADS, 1)
router_mma(const float* __restrict__ h, const float* __restrict__ proto,
           float* __restrict__ out, int T) {
    extern __shared__ char smem[];
    const uint32_t smem_u = smem_u32(smem);
    const int tid  = threadIdx.x;
    const int wid  = tid >> 5;
    const int lane = tid & 31;
    const int t0   = blockIdx.x * BM;

    if (tid < BN) ((float*)(smem + OFF_INVP))[tid] = g_inv_pnorm[tid];

    // A load/convert mapping: row = tid>>2, q = tid&3 -> 8 floats of the 32-chunk
    const int arow_g = tid >> 2;
    const int q      = tid & 3;
    const int k16q   = q >> 1;
    const int halfq  = q & 1;
    const float* ag = h + (size_t)(t0 + arow_g) * DK + q * 8;
    const uint32_t st_a = (uint32_t)k16q * 4096u + (uint32_t)arow_g * 32u
                        + (uint32_t)((halfq ^ ((arow_g >> 2) & 1)) * 16);

    // warp tile: 64 (M) x 32 (N), K-split
    const int ksel    = wid >> 3;                 // 0/1: owned k16 half
    const int warp_m  = ((wid >> 2) & 1) * 64;
    const int warp_n4 = (wid & 3) * 2;
    const uint32_t koff_a = (uint32_t)ksel * 4096u;
    const uint32_t koff_b = (uint32_t)ksel * 8192u;
    const uint32_t bwoff  = (uint32_t)warp_n4 * 512u + (uint32_t)lane * 16u;

    uint32_t aoff[4];
#pragma unroll
    for (int mi = 0; mi < 4; mi++) {
        int ar = warp_m + mi * 16 + ((lane >> 3) & 1) * 8 + (lane & 7);
        int kh = lane >> 4;
        aoff[mi] = (uint32_t)ar * 32u + (uint32_t)((kh ^ ((ar >> 2) & 1)) * 16);
    }

    float acc[4][4][4];
#pragma unroll
    for (int a = 0; a < 4; a++)
#pragma unroll
        for (int b = 0; b < 4; b++)
#pragma unroll
            for (int c = 0; c < 4; c++) acc[a][b][c] = 0.f;

    float hsum = 0.f;
    float4 av0, av1;

    // ---- prologue ----
#pragma unroll
    for (int s = 0; s < 3; s++) {      // B stages 0..2 cp.async
        uint32_t d = smem_u + OFF_B + (uint32_t)s * B_STAGE + (uint32_t)tid * 32u;
        const char* g = (const char*)g_bfrag + (size_t)s * B_STAGE + (size_t)tid * 32;
        CP_ASYNC16(d, g); CP_ASYNC16(d + 16, g + 16);
        CP_COMMIT();
    }
    // A chunks 0,1 -> buffers 0,1; av = chunk 2
#pragma unroll
    for (int c = 0; c < 2; c++) {
        av0 = ((const float4*)(ag + (size_t)c * CHUNK))[0];
        av1 = ((const float4*)(ag + (size_t)c * CHUNK))[1];
        uint32_t u0 = cvt2(av0.x, av0.y), u1 = cvt2(av0.z, av0.w);
        uint32_t u2 = cvt2(av1.x, av1.y), u3 = cvt2(av1.z, av1.w);
        hsum += av0.x*av0.x + av0.y*av0.y + av0.z*av0.z + av0.w*av0.w
              + av1.x*av1.x + av1.y*av1.y + av1.z*av1.z + av1.w*av1.w;
        *(uint4*)(smem + (uint32_t)c * A_STAGE + st_a) = make_uint4(u0, u1, u2, u3);
    }
    av0 = ((const float4*)(ag + 2 * CHUNK))[0];
    av1 = ((const float4*)(ag + 2 * CHUNK))[1];
    CP_WAIT1();
    __syncthreads();

    // pre-barrier preloads for stage 0: A frags (own k16) + B frags
    uint32_t A[4][4];
    uint4 bh0, bh1, bl0, bl1;
    ldm4(A[0], smem_u + koff_a + aoff[0]);
    ldm4(A[1], smem_u + koff_a + aoff[1]);
    ldm4(A[2], smem_u + koff_a + aoff[2]);
    ldm4(A[3], smem_u + koff_a + aoff[3]);
    {
        uint32_t bb = smem_u + OFF_B + koff_b;
        bh0 = lds128(bb + bwoff);        bh1 = lds128(bb + bwoff + 512);
        bl0 = lds128(bb + bwoff + 4096); bl1 = lds128(bb + bwoff + 4096 + 512);
    }

    int a_cur = 0, a_wr = 2;
    // ---- main loop: one sync per 32-K stage ----
#pragma unroll 1
    for (int kt = 0; kt < NSTAGE; ++kt) {
        // ===== pass 1: A_h x B_hi (operands already in registers) =====
#pragma unroll
        for (int mi = 0; mi < 4; mi++) {
            mma16816(acc[mi][0], A[mi], bh0.x, bh0.y);
            mma16816(acc[mi][1], A[mi], bh0.z, bh0.w);
            mma16816(acc[mi][2], A[mi], bh1.x, bh1.y);
            mma16816(acc[mi][3], A[mi], bh1.z, bh1.w);
        }
        {   // issue B(kt+3) cp.async
            int ks = kt + 3;
            if (ks < NSTAGE) {
                uint32_t d = smem_u + OFF_B + (uint32_t)(ks & 3) * B_STAGE + (uint32_t)tid * 32u;
                const char* g = (const char*)g_bfrag + (size_t)ks * B_STAGE + (size_t)tid * 32;
                CP_ASYNC16(d, g); CP_ASYNC16(d + 16, g + 16);
            }
            CP_COMMIT();
        }
        // convert chunk kt+2 -> buffer a_wr (background)
        if (kt + 2 < NSTAGE) {
            char* stg = smem + (uint32_t)a_wr * A_STAGE;
            uint32_t u0 = cvt2(av0.x, av0.y), u1 = cvt2(av0.z, av0.w);
            uint32_t u2 = cvt2(av1.x, av1.y), u3 = cvt2(av1.z, av1.w);
            hsum += av0.x*av0.x + av0.y*av0.y + av0.z*av0.z + av0.w*av0.w
                  + av1.x*av1.x + av1.y*av1.y + av1.z*av1.z + av1.w*av1.w;
            *(uint4*)(stg + st_a) = make_uint4(u0, u1, u2, u3);
        }

        // ===== pass 2: A_h x B_lo =====
#pragma unroll
        for (int mi = 0; mi < 4; mi++) {
            mma16816(acc[mi][0], A[mi], bl0.x, bl0.y);
            mma16816(acc[mi][1], A[mi], bl0.z, bl0.w);
            mma16816(acc[mi][2], A[mi], bl1.x, bl1.y);
            mma16816(acc[mi][3], A[mi], bl1.z, bl1.w);
        }
        {   // prefetch A chunk kt+3
            int ka = (kt + 3 < NSTAGE) ? kt + 3 : NSTAGE - 1;
            av0 = ((const float4*)(ag + (size_t)ka * CHUNK))[0];
            av1 = ((const float4*)(ag + (size_t)ka * CHUNK))[1];
        }

        CP_WAIT1();
        // pre-barrier preloads for stage kt+1:
        // A(kt+1) was written during stage kt-1 (stable since last sync);
        // B slot (kt+1)&3 completed (wait_group 1 retains only kt+2,kt+3 groups)
        {
            int a_nx = a_cur + 1; if (a_nx == 3) a_nx = 0;
            uint32_t na = smem_u + (uint32_t)a_nx * A_STAGE + koff_a;
            ldm4(A[0], na + aoff[0]);
            ldm4(A[1], na + aoff[1]);
            ldm4(A[2], na + aoff[2]);
            ldm4(A[3], na + aoff[3]);
            uint32_t nb = smem_u + OFF_B + (uint32_t)((kt + 1) & 3) * B_STAGE + koff_b;
            bh0 = lds128(nb + bwoff);        bh1 = lds128(nb + bwoff + 512);
            bl0 = lds128(nb + bwoff + 4096); bl1 = lds128(nb + bwoff + 4096 + 512);
            a_cur = a_nx;
            a_wr = a_wr + 1; if (a_wr == 3) a_wr = 0;
        }
        __syncthreads();
    }

    // ---- token norms ----
    ((float*)(smem + OFF_HSQ))[tid] = hsum;
    __syncthreads();
    if (tid < BM) {
        const float* hsq = (const float*)(smem + OFF_HSQ);
        float s = hsq[4 * tid] + hsq[4 * tid + 1] + hsq[4 * tid + 2] + hsq[4 * tid + 3];
        ((float*)(smem + OFF_INVH))[tid] = 1.0f / (sqrtf(s) + 1e-6f);
    }
    __syncthreads();

    // ---- accumulators -> raw dot sums (two-phase K-group reduce, overlay) ----
    {
        float* sims = (float*)(smem + OFF_SIMS);
        const int warp_n = (wid & 3) * 32;
        int lr = lane >> 2, lc = (lane & 3) * 2;
        if (ksel == 0) {
#pragma unroll
            for (int mi = 0; mi < 4; mi++) {
                int row = warp_m + mi * 16 + lr;
#pragma unroll
                for (int nf = 0; nf < 4; nf++) {
                    int col = warp_n + nf * 8 + lc;
                    sims[row * LDS_ + col]           = acc[mi][nf][0];
                    sims[row * LDS_ + col + 1]       = acc[mi][nf][1];
                    sims[(row + 8) * LDS_ + col]     = acc[mi][nf][2];
                    sims[(row + 8) * LDS_ + col + 1] = acc[mi][nf][3];
                }
            }
        }
        __syncthreads();
        if (ksel == 1) {
#pragma unroll
            for (int mi = 0; mi < 4; mi++) {
                int row = warp_m + mi * 16 + lr;
#pragma unroll
                for (int nf = 0; nf < 4; nf++) {
                    int col = warp_n + nf * 8 + lc;
                    sims[row * LDS_ + col]           += acc[mi][nf][0];
                    sims[row * LDS_ + col + 1]       += acc[mi][nf][1];
                    sims[(row + 8) * LDS_ + col]     += acc[mi][nf][2];
                    sims[(row + 8) * LDS_ + col + 1] += acc[mi][nf][3];
                }
            }
        }
    }
    __syncthreads();

    // ---- per-token router (norms inline) + exact boundary recheck ----
    const float* sims = (const float*)(smem + OFF_SIMS);
    const float* invh = (const float*)(smem + OFF_INVH);
    const float* invp = (const float*)(smem + OFF_INVP);
    float* out_mask = out;
    float* out_prob = out + (size_t)T * EE;
    float* out_lc   = out + (size_t)2 * T * EE;
    float* out_ls   = out + (size_t)3 * T * EE;

    for (int rr = wid; rr < BM; rr += 16) {
        const float* srow = &sims[rr * LDS_];
        const float ih = invh[rr];
        float l0, l1;
        {
            float s0 = srow[2 * lane] * ih * invp[2 * lane];
            float s1 = srow[2 * lane + 1] * ih * invp[2 * lane + 1];
            float m = fmaxf(s0, s1);
            l0 = 10.0f * (m + logf(expf(s0 - m) + expf(s1 - m)));
            s0 = srow[64 + 2 * lane] * ih * invp[64 + 2 * lane];
            s1 = srow[64 + 2 * lane + 1] * ih * invp[64 + 2 * lane + 1];
            m = fmaxf(s0, s1);
            l1 = 10.0f * (m + logf(expf(s0 - m) + expf(s1 - m)));
        }

        bool sel0 = false, sel1 = false;
        float mx = -INFINITY, tau = -INFINITY;
#pragma unroll
        for (int it = 0; it < TOPK; ++it) {
            float v0 = sel0 ? -INFINITY : l0;
            float v1 = sel1 ? -INFINITY : l1;
            float v; int idx;
            if (v0 >= v1) { v = v0; idx = lane; }
            else          { v = v1; idx = lane + 32; }
            for (int o = 16; o; o >>= 1) {
                float ov = __shfl_down_sync(FULLM, v, o);
                int   oi = __shfl_down_sync(FULLM, idx, o);
                if (ov > v || (ov == v && oi < idx)) { v = ov; idx = oi; }
            }
            int   w  = __shfl_sync(FULLM, idx, 0);
            float wv = __shfl_sync(FULLM, v, 0);
            if (it == 0) mx = wv;
            if (it == TOPK - 1) tau = wv;
            if (w == lane)           sel0 = true;
            else if (w == lane + 32) sel1 = true;
        }

        // exact recheck of boundary candidates
        bool unc0 = fabsf(l0 - tau) < WWIN;
        bool unc1 = fabsf(l1 - tau) < WWIN;
        unsigned u0 = __ballot_sync(FULLM, unc0);
        unsigned u1 = __ballot_sync(FULLM, unc1);
        if (__popc(u0) + __popc(u1) > 1) {
            const float* hrow = h + (size_t)(t0 + rr) * DK;
            float e0 = l0, e1 = l1;
            unsigned m = u0;
            while (m) {
                int b = __ffs(m) - 1; m &= m - 1;
                float L = exact_logit(hrow, proto, b, ih, invp, lane);
                if (lane == b) e0 = L;
            }
            m = u1;
            while (m) {
                int b = __ffs(m) - 1; m &= m - 1;
                float L = exact_logit(hrow, proto, b + 32, ih, invp, lane);
                if (lane == b) e1 = L;
            }
            bool s0safe = sel0 && !unc0, s1safe = sel1 && !unc1;
            int nsafe = __popc(__ballot_sync(FULLM, s0safe))
                      + __popc(__ballot_sync(FULLM, s1safe));
            int r = TOPK - nsafe;
            sel0 = s0safe; sel1 = s1safe;
            bool rem0 = unc0, rem1 = unc1;
            for (int it = 0; it < r; ++it) {
                float v0 = rem0 ? e0 : -INFINITY;
                float v1 = rem1 ? e1 : -INFINITY;
                float v; int idx;
                if (v0 >= v1) { v = v0; idx = lane; }
                else          { v = v1; idx = lane + 32; }
                for (int o = 16; o; o >>= 1) {
                    float ov = __shfl_down_sync(FULLM, v, o);
                    int   oi = __shfl_down_sync(FULLM, idx, o);
                    if (ov > v || (ov == v && oi < idx)) { v = ov; idx = oi; }
                }
                int w = __shfl_sync(FULLM, idx, 0);
                if (w == lane)           { sel0 = true; rem0 = false; }
                else if (w == lane + 32) { sel1 = true; rem1 = false; }
            }
        }

        float z0 = expf(l0 - mx), z1 = expf(l1 - mx);
        float zs = z0 + z1;
        for (int o = 16; o; o >>= 1) zs += __shfl_xor_sync(FULLM, zs, o);
        float d0 = z0 / zs, d1 = z1 / zs;
        float ms = (sel0 ? d0 : 0.f) + (sel1 ? d1 : 0.f);
        for (int o = 16; o; o >>= 1) ms += __shfl_xor_sync(FULLM, ms, o);
        float inv = 1.0f / (ms + 1e-9f);
        float p0 = sel0 ? d0 * inv : 0.f;
        float p1 = sel1 ? d1 * inv : 0.f;

        size_t bb = (size_t)(t0 + rr) * EE;
        out_mask[bb + lane]      = sel0 ? 1.f : 0.f;
        out_mask[bb + lane + 32] = sel1 ? 1.f : 0.f;
        out_prob[bb + lane]      = p0;
        out_prob[bb + lane + 32] = p1;
        out_lc[bb + lane]        = l0;
        out_lc[bb + lane + 32]   = l1;
        out_ls[bb + lane]        = l0;
        out_ls[bb + lane + 32]   = l1;
    }
}

// ---------------------------------------------------------------------------
extern "C" void kernel_launch(void* const* d_in, const int* in_sizes, int n_in,
                              void* d_out, int out_size) {
    const float* h     = (const float*)d_in[0];
    const float* proto = (const float*)d_in[1];
    float* out = (float*)d_out;
    int T = in_sizes[0] / DK;   // 16384

    prep_kernel<<<640, 256>>>(proto);

    static bool attr_set = false;
    if (!attr_set) {
        cudaFuncSetAttribute(router_mma,
                             cudaFuncAttributeMaxDynamicSharedMemorySize,
                             SMEM_TOTAL);
        attr_set = true;
    }
    router_mma<<<T / BM, NTHREADS, SMEM_TOTAL>>>(h, proto, out, T);
}

// round 16
// speedup vs baseline: 1.0525x; 1.0525x over previous
#include <cuda_runtime.h>
#include <cuda_fp16.h>
#include <math.h>
#include <stdint.h>

// ---------------- problem constants ----------------
#define DK   4096
#define EE   64
#define TOPK 8
#define BM   128
#define BN   128
#define CHUNK 32                 // K floats per stage
#define NSTAGE 128
#define NTHREADS 512
#define FULLM 0xffffffffu

// ---------------- smem layout (bytes) ----------------
#define A_STAGE 16384            // [k16(2)][plane(2)][128 rows][32B]
#define B_STAGE 16384            // [k16][pass][n16][lane] uint4
#define OFF_A 0
#define OFF_B (2*A_STAGE)                 // 32768
#define OFF_SIMS (OFF_B + 4*B_STAGE)      // 98304
#define LDS_ 132
#define OFF_HSQ  (OFF_SIMS + 128*LDS_*4)  // 165888
#define OFF_INVH (OFF_HSQ + 512*4)
#define OFF_INVP (OFF_INVH + 128*4)
#define SMEM_TOTAL (OFF_INVP + 128*4)

__device__ float g_inv_pnorm[BN];
// B fragments: [kt(128)][k16(2)][pass(2)][n16(8)][lane(32)] -> uint4
__device__ uint4 g_bfrag[NSTAGE * 2 * 2 * 8 * 32];

// ---------------- helpers ----------------
__device__ __forceinline__ uint32_t smem_u32(const void* p) {
    uint32_t a;
    asm("{ .reg .u64 t; cvta.to.shared.u64 t, %1; cvt.u32.u64 %0, t; }" : "=r"(a) : "l"(p));
    return a;
}
__device__ __forceinline__ void ldm4(uint32_t* r, uint32_t addr) {
    asm volatile("ldmatrix.sync.aligned.m8n8.x4.shared.b16 {%0,%1,%2,%3}, [%4];"
        : "=r"(r[0]), "=r"(r[1]), "=r"(r[2]), "=r"(r[3]) : "r"(addr));
}
__device__ __forceinline__ uint4 lds128(uint32_t addr) {
    uint4 v;
    asm volatile("ld.shared.v4.u32 {%0,%1,%2,%3}, [%4];"
        : "=r"(v.x), "=r"(v.y), "=r"(v.z), "=r"(v.w) : "r"(addr));
    return v;
}
__device__ __forceinline__ void mma16816(float* c, const uint32_t* a, uint32_t b0, uint32_t b1) {
    asm volatile("mma.sync.aligned.m16n8k16.row.col.f32.f16.f16.f32 "
        "{%0,%1,%2,%3}, {%4,%5,%6,%7}, {%8,%9}, {%0,%1,%2,%3};"
        : "+f"(c[0]), "+f"(c[1]), "+f"(c[2]), "+f"(c[3])
        : "r"(a[0]), "r"(a[1]), "r"(a[2]), "r"(a[3]), "r"(b0), "r"(b1));
}
__device__ __forceinline__ void split2(float x, float y, uint32_t& uh, uint32_t& ul) {
    asm("cvt.rn.f16x2.f32 %0, %1, %2;" : "=r"(uh) : "f"(y), "f"(x));
    float lx = __half2float(__ushort_as_half((unsigned short)(uh & 0xffffu)));
    float ly = __half2float(__ushort_as_half((unsigned short)(uh >> 16)));
    float rx = x - lx, ry = y - ly;
    asm("cvt.rn.f16x2.f32 %0, %1, %2;" : "=r"(ul) : "f"(ry), "f"(rx));
}
#define CP_ASYNC16(dst, src) \
    asm volatile("cp.async.cg.shared.global [%0], [%1], 16;" :: "r"(dst), "l"(src))
#define CP_COMMIT() asm volatile("cp.async.commit_group;" ::: "memory")
#define CP_WAIT1()  asm volatile("cp.async.wait_group 1;"  ::: "memory")

// ---------------------------------------------------------------------------
// Kernel 1: fused prep — blocks [0,512): B split; blocks [512,640): proto norms
// (B-fragment indexing identical to the round-6 bsplit kernel)
// ---------------------------------------------------------------------------
__global__ void prep_kernel(const float* __restrict__ proto) {
    if (blockIdx.x < 512) {
        int idx  = blockIdx.x * 256 + threadIdx.x;     // 131072 uint4
        int lane = idx & 31;
        int n16  = (idx >> 5) & 7;
        int pass = (idx >> 8) & 1;
        int k16  = (idx >> 9) & 1;
        int kt   = idx >> 10;
        int kt16 = kt * 2 + k16;
        uint32_t w[4];
#pragma unroll
        for (int r = 0; r < 4; r++) {
            int n  = n16 * 16 + ((r & 2) << 2) + (lane >> 2);
            int k0 = kt16 * 16 + (r & 1) * 8 + 2 * (lane & 3);
            float x = proto[(size_t)n * DK + k0];
            float y = proto[(size_t)n * DK + k0 + 1];
            uint32_t uh, ul;
            split2(x, y, uh, ul);
            w[r] = pass ? ul : uh;
        }
        g_bfrag[idx] = make_uint4(w[0], w[1], w[2], w[3]);
    } else {
        int row = blockIdx.x - 512;
        const float4* p = reinterpret_cast<const float4*>(proto + (size_t)row * DK);
        float s = 0.f;
        for (int i = threadIdx.x; i < DK / 4; i += blockDim.x) {
            float4 v = p[i];
            s += v.x * v.x + v.y * v.y + v.z * v.z + v.w * v.w;
        }
        for (int o = 16; o; o >>= 1) s += __shfl_down_sync(FULLM, s, o);
        __shared__ float sm[8];
        if ((threadIdx.x & 31) == 0) sm[threadIdx.x >> 5] = s;
        __syncthreads();
        if (threadIdx.x == 0) {
            float t = 0.f;
            for (int i = 0; i < (int)(blockDim.x >> 5); i++) t += sm[i];
            g_inv_pnorm[row] = 1.0f / (sqrtf(t) + 1e-6f);
        }
    }
}

// ---------------------------------------------------------------------------
// Kernel 2: 3-pass split-fp16 mma GEMM (round-6 configuration, measured 172us)
// ---------------------------------------------------------------------------
extern "C" __global__ void __launch_bounds__(NTHREADS, 1)
router_mma(const float* __restrict__ h, float* __restrict__ out, int T) {
    extern __shared__ char smem[];
    const uint32_t smem_u = smem_u32(smem);
    const int tid  = threadIdx.x;
    const int wid  = tid >> 5;
    const int lane = tid & 31;
    const int t0   = blockIdx.x * BM;

    if (tid < BN) ((float*)(smem + OFF_INVP))[tid] = g_inv_pnorm[tid];

    // A load/convert mapping: row = tid>>2, q = tid&3 -> 8 floats of the 32-chunk
    const int arow_g = tid >> 2;
    const int q      = tid & 3;
    const int k16q   = q >> 1;
    const int halfq  = q & 1;
    const float* ag = h + (size_t)(t0 + arow_g) * DK + q * 8;
    const uint32_t st_hi = OFF_A + (uint32_t)k16q * 8192u + (uint32_t)arow_g * 32u
                         + (uint32_t)((halfq ^ ((arow_g >> 2) & 1)) * 16);
    const uint32_t st_lo = st_hi + 4096u;

    // B cp.async mapping: 32B per thread per stage
    const char* bgp = (const char*)g_bfrag;
    const uint32_t bsts = OFF_B + (uint32_t)tid * 32u;

    // warp tile: 32 (M) x 32 (N)
    const int warp_m  = (wid >> 2) * 32;
    const int warp_n4 = (wid & 3) * 2;

    uint32_t aoff[2];
#pragma unroll
    for (int mi = 0; mi < 2; mi++) {
        int ar = warp_m + mi * 16 + ((lane >> 3) & 1) * 8 + (lane & 7);
        int kh = lane >> 4;
        aoff[mi] = (uint32_t)ar * 32u + (uint32_t)((kh ^ ((ar >> 2) & 1)) * 16);
    }
    const uint32_t boff = (uint32_t)warp_n4 * 512u + (uint32_t)lane * 16u;

    float acc[2][4][4];
#pragma unroll
    for (int a = 0; a < 2; a++)
#pragma unroll
        for (int b = 0; b < 4; b++)
#pragma unroll
            for (int c = 0; c < 4; c++) acc[a][b][c] = 0.f;

    float hsum = 0.f;
    float4 av0, av1;

    // ---- prologue: B stages 0..2 via cp.async; A chunk 0 convert+store ----
#pragma unroll
    for (int s = 0; s < 3; s++) {
        uint32_t d = smem_u + bsts + (uint32_t)s * B_STAGE;
        const char* g = bgp + (size_t)s * B_STAGE + (size_t)tid * 32;
        CP_ASYNC16(d, g); CP_ASYNC16(d + 16, g + 16);
        CP_COMMIT();
    }
    av0 = ((const float4*)ag)[0]; av1 = ((const float4*)ag)[1];
    {
        uint32_t uh[4], ul[4];
        split2(av0.x, av0.y, uh[0], ul[0]);
        split2(av0.z, av0.w, uh[1], ul[1]);
        split2(av1.x, av1.y, uh[2], ul[2]);
        split2(av1.z, av1.w, uh[3], ul[3]);
        hsum += av0.x*av0.x + av0.y*av0.y + av0.z*av0.z + av0.w*av0.w
              + av1.x*av1.x + av1.y*av1.y + av1.z*av1.z + av1.w*av1.w;
        *(uint4*)(smem + st_hi) = make_uint4(uh[0], uh[1], uh[2], uh[3]);
        *(uint4*)(smem + st_lo) = make_uint4(ul[0], ul[1], ul[2], ul[3]);
    }
    av0 = ((const float4*)(ag + CHUNK))[0];
    av1 = ((const float4*)(ag + CHUNK))[1];
    CP_WAIT1();
    __syncthreads();

    // preload stage-0 k16=0 B fragments into registers
    uint4 nbh0, nbh1, nbl0, nbl1;
    {
        uint32_t nbb = smem_u + OFF_B;
        nbh0 = lds128(nbb + boff);
        nbh1 = lds128(nbb + boff + 512);
        nbl0 = lds128(nbb + boff + 4096);
        nbl1 = lds128(nbb + boff + 4096 + 512);
    }

    // ---- main loop: one sync per 32-K stage ----
#pragma unroll 1
    for (int kt = 0; kt < NSTAGE; ++kt) {
        const uint32_t abase = smem_u + OFF_A + (uint32_t)(kt & 1) * A_STAGE;
        const uint32_t bbase = smem_u + OFF_B + (uint32_t)(kt & 3) * B_STAGE;

        // ================= k16 = 0 : all operands upfront =================
        uint32_t Ah[2][4], Al[2][4];
        ldm4(Ah[0], abase + aoff[0]);
        ldm4(Ah[1], abase + aoff[1]);
        ldm4(Al[0], abase + 4096u + aoff[0]);
        ldm4(Al[1], abase + 4096u + aoff[1]);
        uint4 bh0 = nbh0, bh1 = nbh1, bl0 = nbl0, bl1 = nbl1;

#pragma unroll
        for (int mi = 0; mi < 2; mi++) {              // A_hi x B_hi
            mma16816(acc[mi][0], Ah[mi], bh0.x, bh0.y);
            mma16816(acc[mi][1], Ah[mi], bh0.z, bh0.w);
            mma16816(acc[mi][2], Ah[mi], bh1.x, bh1.y);
            mma16816(acc[mi][3], Ah[mi], bh1.z, bh1.w);
        }
        // issue B(kt+3) cp.async
        {
            int ks = kt + 3;
            if (ks < NSTAGE) {
                uint32_t d = smem_u + bsts + (uint32_t)(ks & 3) * B_STAGE;
                const char* g = bgp + (size_t)ks * B_STAGE + (size_t)tid * 32;
                CP_ASYNC16(d, g); CP_ASYNC16(d + 16, g + 16);
            }
            CP_COMMIT();
        }
#pragma unroll
        for (int mi = 0; mi < 2; mi++) {              // A_hi x B_lo
            mma16816(acc[mi][0], Ah[mi], bl0.x, bl0.y);
            mma16816(acc[mi][1], Ah[mi], bl0.z, bl0.w);
            mma16816(acc[mi][2], Ah[mi], bl1.x, bl1.y);
            mma16816(acc[mi][3], Ah[mi], bl1.z, bl1.w);
        }

        // convert + store A chunk kt+1 into the other buffer
        if (kt + 1 < NSTAGE) {
            char* stg = smem + ((kt + 1) & 1) * A_STAGE;
            uint32_t uh[4], ul[4];
            split2(av0.x, av0.y, uh[0], ul[0]);
            split2(av0.z, av0.w, uh[1], ul[1]);
            split2(av1.x, av1.y, uh[2], ul[2]);
            split2(av1.z, av1.w, uh[3], ul[3]);
            hsum += av0.x*av0.x + av0.y*av0.y + av0.z*av0.z + av0.w*av0.w
                  + av1.x*av1.x + av1.y*av1.y + av1.z*av1.z + av1.w*av1.w;
            *(uint4*)(stg + st_hi) = make_uint4(uh[0], uh[1], uh[2], uh[3]);
            *(uint4*)(stg + st_lo) = make_uint4(ul[0], ul[1], ul[2], ul[3]);
        }

#pragma unroll
        for (int mi = 0; mi < 2; mi++) {              // A_lo x B_hi
            mma16816(acc[mi][0], Al[mi], bh0.x, bh0.y);
            mma16816(acc[mi][1], Al[mi], bh0.z, bh0.w);
            mma16816(acc[mi][2], Al[mi], bh1.x, bh1.y);
            mma16816(acc[mi][3], Al[mi], bh1.z, bh1.w);
        }

        // ================= k16 = 1 : all operands upfront =================
        ldm4(Ah[0], abase + 8192u + aoff[0]);
        ldm4(Ah[1], abase + 8192u + aoff[1]);
        ldm4(Al[0], abase + 8192u + 4096u + aoff[0]);
        ldm4(Al[1], abase + 8192u + 4096u + aoff[1]);
        bh0 = lds128(bbase + 8192u + boff);
        bh1 = lds128(bbase + 8192u + boff + 512);
        bl0 = lds128(bbase + 8192u + boff + 4096);
        bl1 = lds128(bbase + 8192u + boff + 4096 + 512);

#pragma unroll
        for (int mi = 0; mi < 2; mi++) {              // A_hi x B_hi
            mma16816(acc[mi][0], Ah[mi], bh0.x, bh0.y);
            mma16816(acc[mi][1], Ah[mi], bh0.z, bh0.w);
            mma16816(acc[mi][2], Ah[mi], bh1.x, bh1.y);
            mma16816(acc[mi][3], Ah[mi], bh1.z, bh1.w);
        }
        // prefetch A chunk kt+2
        {
            int ka = (kt + 2 < NSTAGE) ? kt + 2 : NSTAGE - 1;
            av0 = ((const float4*)(ag + (size_t)ka * CHUNK))[0];
            av1 = ((const float4*)(ag + (size_t)ka * CHUNK))[1];
        }
#pragma unroll
        for (int mi = 0; mi < 2; mi++) {              // A_hi x B_lo
            mma16816(acc[mi][0], Ah[mi], bl0.x, bl0.y);
            mma16816(acc[mi][1], Ah[mi], bl0.z, bl0.w);
            mma16816(acc[mi][2], Ah[mi], bl1.x, bl1.y);
            mma16816(acc[mi][3], Ah[mi], bl1.z, bl1.w);
        }
#pragma unroll
        for (int mi = 0; mi < 2; mi++) {              // A_lo x B_hi
            mma16816(acc[mi][0], Al[mi], bh0.x, bh0.y);
            mma16816(acc[mi][1], Al[mi], bh0.z, bh0.w);
            mma16816(acc[mi][2], Al[mi], bh1.x, bh1.y);
            mma16816(acc[mi][3], Al[mi], bh1.z, bh1.w);
        }

        CP_WAIT1();
        // preload next-stage k16=0 B fragments (visible since last sync)
        {
            uint32_t nbb = smem_u + OFF_B + (uint32_t)((kt + 1) & 3) * B_STAGE;
            nbh0 = lds128(nbb + boff);
            nbh1 = lds128(nbb + boff + 512);
            nbl0 = lds128(nbb + boff + 4096);
            nbl1 = lds128(nbb + boff + 4096 + 512);
        }
        __syncthreads();
    }

    // ---- norms ----
    ((float*)(smem + OFF_HSQ))[tid] = hsum;
    __syncthreads();
    if (tid < BM) {
        const float* hsq = (const float*)(smem + OFF_HSQ);
        float s = hsq[4 * tid] + hsq[4 * tid + 1] + hsq[4 * tid + 2] + hsq[4 * tid + 3];
        ((float*)(smem + OFF_INVH))[tid] = 1.0f / (sqrtf(s) + 1e-6f);
    }
    __syncthreads();

    // ---- accumulators -> scaled cosine sims in smem ----
    {
        const float* invh = (const float*)(smem + OFF_INVH);
        const float* invp = (const float*)(smem + OFF_INVP);
        float* sims = (float*)(smem + OFF_SIMS);
        const int warp_n = (wid & 3) * 32;
        int lr = lane >> 2, lc = (lane & 3) * 2;
#pragma unroll
        for (int mi = 0; mi < 2; mi++) {
            int row = warp_m + mi * 16 + lr;
            float ih0 = invh[row], ih1 = invh[row + 8];
#pragma unroll
            for (int nf = 0; nf < 4; nf++) {
                int col = warp_n + nf * 8 + lc;
                float ip0 = invp[col], ip1 = invp[col + 1];
                sims[row * LDS_ + col]           = acc[mi][nf][0] * ih0 * ip0;
                sims[row * LDS_ + col + 1]       = acc[mi][nf][1] * ih0 * ip1;
                sims[(row + 8) * LDS_ + col]     = acc[mi][nf][2] * ih1 * ip0;
                sims[(row + 8) * LDS_ + col + 1] = acc[mi][nf][3] * ih1 * ip1;
            }
        }
    }
    __syncthreads();

    // ---- per-token router: 16 warps, 8 rows each ----
    const float* sims = (const float*)(smem + OFF_SIMS);
    float* out_mask = out;
    float* out_prob = out + (size_t)T * EE;
    float* out_lc   = out + (size_t)2 * T * EE;
    float* out_ls   = out + (size_t)3 * T * EE;

    for (int rr = wid; rr < BM; rr += 16) {
        const float* srow = &sims[rr * LDS_];
        float l0, l1;
        {
            float s0 = srow[2 * lane], s1 = srow[2 * lane + 1];
            float m = fmaxf(s0, s1);
            l0 = 10.0f * (m + logf(expf(s0 - m) + expf(s1 - m)));
            s0 = srow[64 + 2 * lane]; s1 = srow[64 + 2 * lane + 1];
            m = fmaxf(s0, s1);
            l1 = 10.0f * (m + logf(expf(s0 - m) + expf(s1 - m)));
        }

        bool sel0 = false, sel1 = false;
        float mx = -INFINITY;
#pragma unroll
        for (int it = 0; it < TOPK; ++it) {
            float v0 = sel0 ? -INFINITY : l0;
            float v1 = sel1 ? -INFINITY : l1;
            float v; int idx;
            if (v0 >= v1) { v = v0; idx = lane; }
            else          { v = v1; idx = lane + 32; }
            for (int o = 16; o; o >>= 1) {
                float ov = __shfl_down_sync(FULLM, v, o);
                int   oi = __shfl_down_sync(FULLM, idx, o);
                if (ov > v || (ov == v && oi < idx)) { v = ov; idx = oi; }
            }
            int   w  = __shfl_sync(FULLM, idx, 0);
            float wv = __shfl_sync(FULLM, v, 0);
            if (it == 0) mx = wv;
            if (w == lane)           sel0 = true;
            else if (w == lane + 32) sel1 = true;
        }

        float z0 = expf(l0 - mx), z1 = expf(l1 - mx);
        float zs = z0 + z1;
        for (int o = 16; o; o >>= 1) zs += __shfl_xor_sync(FULLM, zs, o);
        float d0 = z0 / zs, d1 = z1 / zs;
        float ms = (sel0 ? d0 : 0.f) + (sel1 ? d1 : 0.f);
        for (int o = 16; o; o >>= 1) ms += __shfl_xor_sync(FULLM, ms, o);
        float inv = 1.0f / (ms + 1e-9f);
        float p0 = sel0 ? d0 * inv : 0.f;
        float p1 = sel1 ? d1 * inv : 0.f;

        size_t bb = (size_t)(t0 + rr) * EE;
        out_mask[bb + lane]      = sel0 ? 1.f : 0.f;
        out_mask[bb + lane + 32] = sel1 ? 1.f : 0.f;
        out_prob[bb + lane]      = p0;
        out_prob[bb + lane + 32] = p1;
        out_lc[bb + lane]        = l0;
        out_lc[bb + lane + 32]   = l1;
        out_ls[bb + lane]        = l0;
        out_ls[bb + lane + 32]   = l1;
    }
}

// ---------------------------------------------------------------------------
extern "C" void kernel_launch(void* const* d_in, const int* in_sizes, int n_in,
                              void* d_out, int out_size) {
    const float* h     = (const float*)d_in[0];
    const float* proto = (const float*)d_in[1];
    float* out = (float*)d_out;
    int T = in_sizes[0] / DK;   // 16384

    prep_kernel<<<640, 256>>>(proto);

    static bool attr_set = false;
    if (!attr_set) {
        cudaFuncSetAttribute(router_mma,
                             cudaFuncAttributeMaxDynamicSharedMemorySize,
                             SMEM_TOTAL);
        attr_set = true;
    }
    router_mma<<<T / BM, NTHREADS, SMEM_TOTAL>>>(h, out, T);
}